// round 16
// baseline (speedup 1.0000x reference)
#include <cuda_runtime.h>
#include <cuda_fp16.h>
#include <cstdint>
#include <math.h>

#define D_MODEL 1024
#define N_HEADS 16
#define HEAD_DIM 64
#define BATCH 2
#define SEQ 2048
#define M_TOT (BATCH * SEQ)   // 4096
#define WN (D_MODEL * D_MODEL)
#define PERS_CTAS 296

// ---------------- scratch (no allocations allowed) ----------------
__device__ __half g_x_hi[M_TOT * D_MODEL];
__device__ __half g_w_hi[4 * WN];   // wq,wk,wv,wo
__device__ __half g_qh[M_TOT * D_MODEL];    // [b,h,s,d]
__device__ __half g_kh[M_TOT * D_MODEL];    // [b,h,s,d]
__device__ __half g_vth[M_TOT * D_MODEL];   // [h*64+d][b*2048+s]
__device__ __half g_ah[M_TOT * D_MODEL];    // [m][1024]
__device__ int g_ctr_qkv, g_ctr_at, g_ctr_o;
__device__ int g_done[32];                  // per (b*16 + qt) attention completion
__device__ int g_bar_count;
__device__ volatile int g_bar_phase;

// =================== portable PTX helpers ===================
__device__ __forceinline__ uint32_t smem_u32(const void* p) {
    uint32_t a;
    asm("{ .reg .u64 t; cvta.to.shared.u64 t, %1; cvt.u32.u64 %0, t; }"
        : "=r"(a) : "l"(p));
    return a;
}

__device__ __forceinline__ void ldsm_x4(uint32_t* r, uint32_t addr) {
    asm volatile("ldmatrix.sync.aligned.m8n8.x4.shared.b16 {%0,%1,%2,%3}, [%4];"
                 : "=r"(r[0]), "=r"(r[1]), "=r"(r[2]), "=r"(r[3]) : "r"(addr));
}

// D += A * B  (m16n8k16, fp16 in, fp32 acc)
__device__ __forceinline__ void mma_f16(float* d, const uint32_t* a,
                                        uint32_t b0, uint32_t b1) {
    asm volatile(
        "mma.sync.aligned.m16n8k16.row.col.f32.f16.f16.f32 "
        "{%0,%1,%2,%3}, {%4,%5,%6,%7}, {%8,%9}, {%0,%1,%2,%3};"
        : "+f"(d[0]), "+f"(d[1]), "+f"(d[2]), "+f"(d[3])
        : "r"(a[0]), "r"(a[1]), "r"(a[2]), "r"(a[3]), "r"(b0), "r"(b1));
}

__device__ __forceinline__ void cp16(void* dst_smem, const void* src) {
    uint32_t d = smem_u32(dst_smem);
    asm volatile("cp.async.cg.shared.global [%0], [%1], 16;" :: "r"(d), "l"(src) : "memory");
}
#define CP_COMMIT() asm volatile("cp.async.commit_group;" ::: "memory")

__device__ __forceinline__ uint32_t pack_h(float v0, float v1) {
    __half2 h = __floats2half2_rn(v0, v1);
    return *(uint32_t*)&h;
}
__device__ __forceinline__ void store_h(__half* Oh, size_t off, float v0, float v1) {
    *(__half2*)(Oh + off) = __floats2half2_rn(v0, v1);
}
__device__ __forceinline__ void pause_() {
    asm volatile("nanosleep.u32 64;");
}

// device-wide barrier (all PERS_CTAS resident by construction)
__device__ __forceinline__ void grid_barrier(int& ph) {
    __syncthreads();
    if (threadIdx.x == 0) {
        __threadfence();
        ph += 1;
        if (atomicAdd(&g_bar_count, 1) == PERS_CTAS - 1) {
            atomicExch(&g_bar_count, 0);
            __threadfence();
            g_bar_phase = ph;
        } else {
            while (g_bar_phase < ph) pause_();
        }
        __threadfence();
    }
    __syncthreads();
}

// =================================================================
// GEMM body: C tile = A[.,1024] @ W[.,1024]^T, plain fp16, fp32 acc.
// cp.async 2-stage, BK=64, 128x128 tile, 8 warps (2m x 4n).
// MODE 0: fp32 row-major C (ldc)
// MODE 2: fp16 -> [b,h,s,d] head layout (Q, K)
// MODE 4: fp16 row-major (ldc)          (V-transposed)
// =================================================================
#define GROW 72                        // smem row stride in halves (64 + 8 pad)
#define GTILE_B (128 * GROW * 2)       // 18432 B per tile
#define GSTAGE (2 * GTILE_B)           // 36864 B per stage (A, B)
#define FUSED_SMEM (2 * GSTAGE)        // 73728 B (gemm stages; attn uses half)

template <int MODE>
__device__ __forceinline__ void gemm_body(
    char* gsm,
    const __half* __restrict__ Ah_g, const __half* __restrict__ Whi,
    float* __restrict__ C, __half* __restrict__ Oh,
    int ldc, int bm, int bn) {
    const int tid = threadIdx.x;
    const int wid = tid >> 5, lane = tid & 31;
    const int wmr = wid >> 2, wnr = wid & 3;

    float acc[4][4][4];
#pragma unroll
    for (int i = 0; i < 4; i++)
#pragma unroll
        for (int j = 0; j < 4; j++)
#pragma unroll
            for (int r = 0; r < 4; r++) acc[i][j][r] = 0.f;

    const int lrow = lane & 15, lcol = (lane >> 4) * 8;

    auto fill = [&](int st, int k0) {
        char* base = gsm + st * GSTAGE;
#pragma unroll
        for (int i = 0; i < 4; i++) {
            int c = tid + i * 256;          // 0..1023 (row, 16B chunk)
            int row = c >> 3, kc = (c & 7) * 8;
            int so = (row * GROW + kc) * 2;
            size_t ga = (size_t)(bm + row) * 1024 + k0 + kc;
            size_t gb = (size_t)(bn + row) * 1024 + k0 + kc;
            cp16(base + so, Ah_g + ga);
            cp16(base + GTILE_B + so, Whi + gb);
        }
        CP_COMMIT();
    };

    fill(0, 0);
    for (int ch = 0; ch < 16; ch++) {
        if (ch + 1 < 16) {
            fill((ch + 1) & 1, (ch + 1) * 64);
            asm volatile("cp.async.wait_group 1;" ::: "memory");
        } else {
            asm volatile("cp.async.wait_group 0;" ::: "memory");
        }
        __syncthreads();
        char* base = gsm + (ch & 1) * GSTAGE;
        __half* sAh = (__half*)base;
        __half* sBh = (__half*)(base + GTILE_B);

#pragma unroll
        for (int ks = 0; ks < 64; ks += 16) {
            uint32_t bh[2][4];
#pragma unroll
            for (int p = 0; p < 2; p++) {
                int off = (wnr * 32 + p * 16 + lrow) * GROW + ks + lcol;
                ldsm_x4(bh[p], smem_u32(sBh + off));
            }
            uint32_t ah[2][4];
            {
                int off = (wmr * 64 + lrow) * GROW + ks + lcol;
                ldsm_x4(ah[0], smem_u32(sAh + off));
            }
#pragma unroll
            for (int mi = 0; mi < 4; mi++) {
                const int cur = mi & 1, nxt = cur ^ 1;
                if (mi < 3) {
                    int off = (wmr * 64 + (mi + 1) * 16 + lrow) * GROW + ks + lcol;
                    ldsm_x4(ah[nxt], smem_u32(sAh + off));
                }
#pragma unroll
                for (int ni = 0; ni < 4; ni++) {
                    int p = ni >> 1, q = ni & 1;
                    mma_f16(acc[mi][ni], ah[cur], bh[p][q], bh[p][q + 2]);
                }
            }
        }
        __syncthreads();
    }

    // ---- epilogue ----
    const int r_in = lane >> 2, c_in = (lane & 3) * 2;
#pragma unroll
    for (int mi = 0; mi < 4; mi++) {
#pragma unroll
        for (int ni = 0; ni < 4; ni++) {
            int m0 = bm + wmr * 64 + mi * 16 + r_in;
            int n  = bn + wnr * 32 + ni * 8 + c_in;
            float v0 = acc[mi][ni][0], v1 = acc[mi][ni][1];
            float v2 = acc[mi][ni][2], v3 = acc[mi][ni][3];
            if (MODE == 0) {
                *(float2*)(C + (size_t)m0 * ldc + n) = make_float2(v0, v1);
                *(float2*)(C + (size_t)(m0 + 8) * ldc + n) = make_float2(v2, v3);
            } else if (MODE == 4) {
                store_h(Oh, (size_t)m0 * ldc + n, v0, v1);
                store_h(Oh, (size_t)(m0 + 8) * ldc + n, v2, v3);
            } else {  // MODE 2: [b,h,s,d]
                int h = n >> 6, d = n & 63;
#pragma unroll
                for (int rr = 0; rr < 2; rr++) {
                    int m = m0 + rr * 8;
                    int b = m >> 11, s = m & 2047;
                    size_t off = ((size_t)((b * N_HEADS + h) * SEQ + s)) * HEAD_DIM + d;
                    store_h(Oh, off, acc[mi][ni][2 * rr], acc[mi][ni][2 * rr + 1]);
                }
            }
        }
    }
}

// =================================================================
// attention item body (identical math to R15)
// =================================================================
#define ASROW 72
#define ABUF_B (64 * ASROW * 2)        // 9216 B per tile buffer
#define ASTAGE (2 * ABUF_B)            // 18432 B per stage (K, V)

__device__ __forceinline__ void attn_item(
    char* asm_raw, int w,
    const __half* __restrict__ Qh, const __half* __restrict__ Kh,
    const __half* __restrict__ Vh, __half* __restrict__ Ohg) {
    auto buf = [&](int st, int t) -> __half* {
        return (__half*)(asm_raw + st * ASTAGE + t * ABUF_B);
    };
    const int tid = threadIdx.x, wid = tid >> 5, lane = tid & 31;
    const int lrow = lane & 15, lcol = (lane >> 4) * 8;
    const int rA = lane >> 2;
    const int tig2 = (lane & 3) * 2;

    const int qt = 15 - (w >> 5);       // LPT: long items first
    const int bh = w & 31;
    const int b = bh >> 4, h = bh & 15;
    const int q0 = qt * 128;
    const size_t qkbase = (size_t)bh * SEQ * HEAD_DIM;
    const size_t vbase = (size_t)(h * 64) * 4096 + (size_t)b * 2048;

    // ---- stage Q into fragments via stage-0 scratch ----
#pragma unroll
    for (int i = 0; i < 4; i++) {
        int c = tid + i * 256;
        int row = c >> 3, cc = (c & 7) * 8;
        __half* dst = buf(0, row < 64 ? 0 : 1) + (row & 63) * ASROW + cc;
        *(uint4*)dst = *(const uint4*)(Qh + qkbase + (size_t)(q0 + row) * 64 + cc);
    }
    __syncthreads();
    uint32_t qfh[4][4];
    {
        int qr = wid * 16 + lrow;
        const __half* bq = buf(0, qr < 64 ? 0 : 1);
        int qrl = qr & 63;
#pragma unroll
        for (int ks = 0; ks < 4; ks++)
            ldsm_x4(qfh[ks], smem_u32(bq + qrl * ASROW + ks * 16 + lcol));
    }
    __syncthreads();   // scratch free before fillKV overwrites it

    auto fillKV = [&](int st, int k0) {
#pragma unroll
        for (int i = 0; i < 2; i++) {
            int c = tid + i * 256;
            int row = c >> 3, cc = (c & 7) * 8;
            int so = row * ASROW + cc;
            cp16(buf(st, 0) + so, Kh + qkbase + (size_t)(k0 + row) * 64 + cc);
            cp16(buf(st, 1) + so, Vh + vbase + (size_t)row * 4096 + k0 + cc);
        }
        CP_COMMIT();
    };

    float oacc[8][4];
#pragma unroll
    for (int i = 0; i < 8; i++)
#pragma unroll
        for (int j = 0; j < 4; j++) oacc[i][j] = 0.f;
    float mMA = -1e30f, mMB = -1e30f, lA = 0.f, lB = 0.f;

    const int nt = 2 * qt + 2;
    fillKV(0, 0);
    for (int jt = 0; jt < nt; jt++) {
        const int k0 = jt * 64;
        if (jt + 1 < nt) {
            fillKV((jt + 1) & 1, (jt + 1) * 64);
            asm volatile("cp.async.wait_group 1;" ::: "memory");
        } else {
            asm volatile("cp.async.wait_group 0;" ::: "memory");
        }
        __syncthreads();
        const int st = jt & 1;
        __half* sKh = buf(st, 0);
        __half* sVh = buf(st, 1);

        const int wrow0 = q0 + wid * 16;
        if (k0 <= wrow0 + 15) {
            // ---- scores S = Q K^T, pipelined K frags ----
            float sacc[8][4];
#pragma unroll
            for (int i = 0; i < 8; i++)
#pragma unroll
                for (int j = 0; j < 4; j++) sacc[i][j] = 0.f;
#pragma unroll
            for (int ks = 0; ks < 4; ks++) {
                uint32_t kfh[2][4];
                {
                    int off = lrow * ASROW + ks * 16 + lcol;   // p = 0
                    ldsm_x4(kfh[0], smem_u32(sKh + off));
                }
#pragma unroll
                for (int p = 0; p < 4; p++) {
                    const int cur = p & 1, nxt = cur ^ 1;
                    if (p < 3) {
                        int off = ((p + 1) * 16 + lrow) * ASROW + ks * 16 + lcol;
                        ldsm_x4(kfh[nxt], smem_u32(sKh + off));
                    }
#pragma unroll
                    for (int qq = 0; qq < 2; qq++) {
                        int ni = 2 * p + qq;
                        mma_f16(sacc[ni], qfh[ks], kfh[cur][qq], kfh[cur][qq + 2]);
                    }
                }
            }
            // ---- scale + causal mask ----
            const bool band = (k0 + 63 > wrow0);
            const int rowAg = wrow0 + rA, rowBg = rowAg + 8;
#pragma unroll
            for (int ni = 0; ni < 8; ni++) {
                int colb = k0 + ni * 8 + tig2;
#pragma unroll
                for (int e = 0; e < 4; e++) {
                    float s = sacc[ni][e] * 0.125f;
                    if (band) {
                        int col = colb + (e & 1);
                        int row = (e < 2) ? rowAg : rowBg;
                        if (col > row) s = -1e30f;
                    }
                    sacc[ni][e] = s;
                }
            }
            // ---- online softmax ----
            float mxA = -1e30f, mxB = -1e30f;
#pragma unroll
            for (int ni = 0; ni < 8; ni++) {
                mxA = fmaxf(mxA, fmaxf(sacc[ni][0], sacc[ni][1]));
                mxB = fmaxf(mxB, fmaxf(sacc[ni][2], sacc[ni][3]));
            }
            mxA = fmaxf(mxA, __shfl_xor_sync(0xffffffffu, mxA, 1));
            mxA = fmaxf(mxA, __shfl_xor_sync(0xffffffffu, mxA, 2));
            mxB = fmaxf(mxB, __shfl_xor_sync(0xffffffffu, mxB, 1));
            mxB = fmaxf(mxB, __shfl_xor_sync(0xffffffffu, mxB, 2));
            float mnA = fmaxf(mMA, mxA), mnB = fmaxf(mMB, mxB);
            float scA = __expf(mMA - mnA), scB = __expf(mMB - mnB);
            mMA = mnA; mMB = mnB;
            float suA = 0.f, suB = 0.f;
#pragma unroll
            for (int ni = 0; ni < 8; ni++) {
                sacc[ni][0] = __expf(sacc[ni][0] - mnA); suA += sacc[ni][0];
                sacc[ni][1] = __expf(sacc[ni][1] - mnA); suA += sacc[ni][1];
                sacc[ni][2] = __expf(sacc[ni][2] - mnB); suB += sacc[ni][2];
                sacc[ni][3] = __expf(sacc[ni][3] - mnB); suB += sacc[ni][3];
            }
            suA += __shfl_xor_sync(0xffffffffu, suA, 1);
            suA += __shfl_xor_sync(0xffffffffu, suA, 2);
            suB += __shfl_xor_sync(0xffffffffu, suB, 1);
            suB += __shfl_xor_sync(0xffffffffu, suB, 2);
            lA = lA * scA + suA;
            lB = lB * scB + suB;
#pragma unroll
            for (int ni = 0; ni < 8; ni++) {
                oacc[ni][0] *= scA; oacc[ni][1] *= scA;
                oacc[ni][2] *= scB; oacc[ni][3] *= scB;
            }
            // ---- O += P * V^T, pipelined V frags ----
#pragma unroll
            for (int j = 0; j < 4; j++) {
                uint32_t Ph[4];
                Ph[0] = pack_h(sacc[2 * j][0],     sacc[2 * j][1]);
                Ph[1] = pack_h(sacc[2 * j][2],     sacc[2 * j][3]);
                Ph[2] = pack_h(sacc[2 * j + 1][0], sacc[2 * j + 1][1]);
                Ph[3] = pack_h(sacc[2 * j + 1][2], sacc[2 * j + 1][3]);
                uint32_t vfh[2][4];
                {
                    int off = lrow * ASROW + j * 16 + lcol;    // p = 0
                    ldsm_x4(vfh[0], smem_u32(sVh + off));
                }
#pragma unroll
                for (int p = 0; p < 4; p++) {
                    const int cur = p & 1, nxt = cur ^ 1;
                    if (p < 3) {
                        int off = ((p + 1) * 16 + lrow) * ASROW + j * 16 + lcol;
                        ldsm_x4(vfh[nxt], smem_u32(sVh + off));
                    }
#pragma unroll
                    for (int qq = 0; qq < 2; qq++) {
                        int ni = 2 * p + qq;
                        mma_f16(oacc[ni], Ph, vfh[cur][qq], vfh[cur][qq + 2]);
                    }
                }
            }
        }
        __syncthreads();   // all warps done with stage st before refill
    }

    // ---- normalize + store fp16 to [m][1024] ----
    float iA = 1.f / lA, iB = 1.f / lB;
    int sA = q0 + wid * 16 + rA;
    size_t rowA_off = ((size_t)b * SEQ + sA) * D_MODEL + h * 64;
    size_t rowB_off = rowA_off + (size_t)8 * D_MODEL;
#pragma unroll
    for (int ni = 0; ni < 8; ni++) {
        int n = ni * 8 + tig2;
        store_h(Ohg, rowA_off + n, oacc[ni][0] * iA, oacc[ni][1] * iA);
        store_h(Ohg, rowB_off + n, oacc[ni][2] * iB, oacc[ni][3] * iB);
    }

    // ---- publish completion of (b, qt) ----
    __threadfence();
    __syncthreads();
    if (tid == 0) atomicAdd(&g_done[(b << 4) + qt], 1);
}

// =================================================================
// the fused persistent kernel: split -> | -> qkv -> | -> attn ~> o
// =================================================================
#define SPLIT_TOT (2 * 1048576)        // x float4s + 4 weights float4s
#define XF4 1048576
#define WF4 262144
#define QKV_TILES 768
#define AT_WORK 512
#define O_TILES 256

__global__ __launch_bounds__(256, 2)
void fused_all(const float* __restrict__ x, const float* __restrict__ wq,
               const float* __restrict__ wk, const float* __restrict__ wv,
               const float* __restrict__ wo,
               __half* __restrict__ xh, __half* __restrict__ wh,
               __half* __restrict__ qh, __half* __restrict__ kh,
               __half* __restrict__ vth, __half* __restrict__ ah,
               float* __restrict__ out) {
    extern __shared__ char gsm[];
    __shared__ int s_tile;
    const int tid = threadIdx.x;

    int phase = g_bar_phase;   // all CTAs read same value (no barrier can
                               // complete before every CTA has arrived)
    if (blockIdx.x == 0 && tid == 0) {
        g_ctr_qkv = 0; g_ctr_at = 0; g_ctr_o = 0;
#pragma unroll
        for (int i = 0; i < 32; i++) g_done[i] = 0;
    }

    // ---------- stage 0: split (grid-stride, static) ----------
    for (int i = blockIdx.x * 256 + tid; i < SPLIT_TOT; i += PERS_CTAS * 256) {
        const float* src;
        __half* hi;
        int off;
        if (i < XF4) {
            src = x; hi = xh; off = i;
        } else {
            int j = i - XF4;
            int w = j >> 18;
            off = j & (WF4 - 1);
            src = (w == 0) ? wq : (w == 1) ? wk : (w == 2) ? wv : wo;
            hi = wh + (size_t)w * WN;
        }
        float4 v = ((const float4*)src)[off];
        __half2 h0 = __floats2half2_rn(v.x, v.y);
        __half2 h1 = __floats2half2_rn(v.z, v.w);
        ((uint2*)hi)[off] = make_uint2(*(uint32_t*)&h0, *(uint32_t*)&h1);
    }
    grid_barrier(phase);

    // ---------- stage 1: fused Q/K/V projections (dynamic) ----------
    while (true) {
        if (tid == 0) s_tile = atomicAdd(&g_ctr_qkv, 1);
        __syncthreads();
        int t = s_tile;
        if (t >= QKV_TILES) break;
        int z = t >> 8;
        int r = t & 255;
        int by = r >> 3, bx = r & 7;
        if (z == 0) {
            gemm_body<2>(gsm, xh, wh, nullptr, qh, 0, by * 128, bx * 128);
        } else if (z == 1) {
            gemm_body<2>(gsm, xh, wh + WN, nullptr, kh, 0, by * 128, bx * 128);
        } else {
            gemm_body<4>(gsm, wh + 2 * (size_t)WN, xh, nullptr, vth, M_TOT,
                         bx * 128, by * 128);
        }
    }
    grid_barrier(phase);

    // ---------- stage 2: attention (dynamic LPT; publishes g_done) ----------
    while (true) {
        if (tid == 0) s_tile = atomicAdd(&g_ctr_at, 1);
        __syncthreads();
        int w = s_tile;
        if (w >= AT_WORK) break;
        attn_item(gsm, w, qh, kh, vth, ah);
    }

    // ---------- stage 3: o-projection (overlaps attention tail) ----------
    const __half* woh = wh + 3 * (size_t)WN;
    while (true) {
        if (tid == 0) {
            int g = atomicAdd(&g_ctr_o, 1);
            s_tile = g;
            if (g < O_TILES) {
                // completion-matched order: qt=15 blocks first
                int pi = g >> 4;
                int sub = g & 15;
                int by = ((sub >> 3) << 4) + (15 - pi);
                while (((volatile int*)g_done)[by] < 16) pause_();
            }
        }
        __syncthreads();
        int g = s_tile;
        if (g >= O_TILES) break;
        __threadfence();
        int pi = g >> 4;
        int sub = g & 15;
        int qt = 15 - pi;
        int b  = sub >> 3;
        int bx = sub & 7;
        int by = b * 16 + qt;
        gemm_body<0>(gsm, ah, woh, out, nullptr, D_MODEL, by * 128, bx * 128);
    }
}

// =================================================================
// launch
// =================================================================
extern "C" void kernel_launch(void* const* d_in, const int* in_sizes, int n_in,
                              void* d_out, int out_size) {
    const float* x  = (const float*)d_in[0];
    const float* wq = (const float*)d_in[1];
    const float* wk = (const float*)d_in[2];
    const float* wv = (const float*)d_in[3];
    const float* wo = (const float*)d_in[4];
    float* out = (float*)d_out;

    __half *xh, *wh, *qh, *kh, *vth, *ah;
    cudaGetSymbolAddress((void**)&xh, g_x_hi);
    cudaGetSymbolAddress((void**)&wh, g_w_hi);
    cudaGetSymbolAddress((void**)&qh, g_qh);
    cudaGetSymbolAddress((void**)&kh, g_kh);
    cudaGetSymbolAddress((void**)&vth, g_vth);
    cudaGetSymbolAddress((void**)&ah, g_ah);

    cudaFuncSetAttribute(fused_all,
                         cudaFuncAttributeMaxDynamicSharedMemorySize, FUSED_SMEM);

    fused_all<<<PERS_CTAS, 256, FUSED_SMEM>>>(x, wq, wk, wv, wo,
                                              xh, wh, qh, kh, vth, ah, out);
}